// round 2
// baseline (speedup 1.0000x reference)
#include <cuda_runtime.h>
#include <cuda_bf16.h>
#include <math.h>

// Problem constants
#define BATCH 4
#define SEQ   2048
#define DM    1024
#define NH    16
#define DK    64
#define MROWS (BATCH * SEQ)      // 8192

// ---------------- scratch (device globals; no runtime alloc) ----------------
__device__ float g_q[MROWS * DM];
__device__ float g_k[MROWS * DM];
__device__ float g_v[MROWS * DM];
__device__ float g_attn[MROWS * DM];

// ---------------- SGEMM with bias: C[M,N] = A[M,K] @ W[K,N] + b --------------
// 128x128 tile, BK=8, 256 threads, 8x8 per-thread micro-tile.
#define PM 128
#define PN 128
#define PKD 8

__global__ __launch_bounds__(256) void gemm_bias_kernel(
    const float* __restrict__ A, const float* __restrict__ W,
    const float* __restrict__ bias, float* __restrict__ C,
    int M, int N, int K)
{
    __shared__ float As[PKD][PM];
    __shared__ float Bs[PKD][PN];

    const int tid = threadIdx.x;
    const int bm = blockIdx.y * PM;
    const int bn = blockIdx.x * PN;

    // A tile load mapping: 128 rows x 8 k -> 256 float4 (one per thread)
    const int arow  = tid >> 1;          // 0..127
    const int acol4 = (tid & 1) * 4;     // 0 or 4
    // B tile load mapping: 8 rows x 128 cols -> 256 float4
    const int brow  = tid >> 5;          // 0..7
    const int bcol4 = (tid & 31) * 4;    // 0..124

    const int tx = tid & 15;             // 0..15 (N dir)
    const int ty = tid >> 4;             // 0..15 (M dir)

    float acc[8][8];
    #pragma unroll
    for (int i = 0; i < 8; i++)
        #pragma unroll
        for (int j = 0; j < 8; j++) acc[i][j] = 0.f;

    for (int k0 = 0; k0 < K; k0 += PKD) {
        float4 a4 = *(const float4*)&A[(size_t)(bm + arow) * K + k0 + acol4];
        As[acol4 + 0][arow] = a4.x;
        As[acol4 + 1][arow] = a4.y;
        As[acol4 + 2][arow] = a4.z;
        As[acol4 + 3][arow] = a4.w;
        *(float4*)&Bs[brow][bcol4] =
            *(const float4*)&W[(size_t)(k0 + brow) * N + bn + bcol4];
        __syncthreads();

        #pragma unroll
        for (int k = 0; k < PKD; k++) {
            float4 ra0 = *(const float4*)&As[k][ty * 8];
            float4 ra1 = *(const float4*)&As[k][ty * 8 + 4];
            float4 rb0 = *(const float4*)&Bs[k][tx * 8];
            float4 rb1 = *(const float4*)&Bs[k][tx * 8 + 4];
            float ra[8] = {ra0.x, ra0.y, ra0.z, ra0.w, ra1.x, ra1.y, ra1.z, ra1.w};
            float rb[8] = {rb0.x, rb0.y, rb0.z, rb0.w, rb1.x, rb1.y, rb1.z, rb1.w};
            #pragma unroll
            for (int i = 0; i < 8; i++)
                #pragma unroll
                for (int j = 0; j < 8; j++)
                    acc[i][j] += ra[i] * rb[j];
        }
        __syncthreads();
    }

    #pragma unroll
    for (int i = 0; i < 8; i++) {
        const int row = bm + ty * 8 + i;
        #pragma unroll
        for (int j = 0; j < 8; j += 4) {
            const int col = bn + tx * 8 + j;
            float4 o;
            o.x = acc[i][j + 0] + bias[col + 0];
            o.y = acc[i][j + 1] + bias[col + 1];
            o.z = acc[i][j + 2] + bias[col + 2];
            o.w = acc[i][j + 3] + bias[col + 3];
            *(float4*)&C[(size_t)row * N + col] = o;
        }
    }
}

// ---------------- Flash attention (fp32, online softmax) --------------------
// Block: 256 threads handles one (b, h, 64-query tile). 32 KV tiles of 64.
// Per-thread: 4x4 score micro-tile, 4x4 output micro-tile.
#define BQ  64
#define BKV 64
#define QS  68                 // padded smem row stride (floats, mult of 4)
#define ATTN_SMEM ((DK * QS /*Qt*/ + DK * QS /*Kt*/ + BKV * DK /*Vs*/ + BKV * QS /*Pt*/) * sizeof(float))

__global__ __launch_bounds__(256) void attn_kernel(
    const float* __restrict__ gq, const float* __restrict__ gk,
    const float* __restrict__ gv, float* __restrict__ gout)
{
    extern __shared__ float sm[];
    float* Qt = sm;                    // [DK][QS]  Qt[d][r]
    float* Kt = Qt + DK * QS;          // [DK][QS]  Kt[d][j]
    float* Vs = Kt + DK * QS;          // [BKV][DK] Vs[j][d]
    float* Pt = Vs + BKV * DK;         // [BKV][QS] Pt[j][r]

    const int tid = threadIdx.x;
    const int tx = tid & 15;           // 0..15
    const int ty = tid >> 4;           // 0..15
    const int q0 = blockIdx.x * BQ;
    const int b  = blockIdx.y >> 4;
    const int h  = blockIdx.y & 15;

    const size_t head_off = (size_t)h * DK;
    const float* qbase = gq + (size_t)b * SEQ * DM + head_off;
    const float* kbase = gk + (size_t)b * SEQ * DM + head_off;
    const float* vbase = gv + (size_t)b * SEQ * DM + head_off;

    // Load Q tile transposed: Qt[d][r]
    for (int i = tid; i < BQ * (DK / 4); i += 256) {
        int r  = i >> 4;
        int c4 = (i & 15) * 4;
        float4 v = *(const float4*)&qbase[(size_t)(q0 + r) * DM + c4];
        Qt[(c4 + 0) * QS + r] = v.x;
        Qt[(c4 + 1) * QS + r] = v.y;
        Qt[(c4 + 2) * QS + r] = v.z;
        Qt[(c4 + 3) * QS + r] = v.w;
    }

    float accO[4][4];
    float m[4], l[4];
    #pragma unroll
    for (int i = 0; i < 4; i++) {
        m[i] = -1e30f; l[i] = 0.f;
        #pragma unroll
        for (int p = 0; p < 4; p++) accO[i][p] = 0.f;
    }

    const float scale = 0.125f;  // 1/sqrt(64)

    for (int kt = 0; kt < SEQ / BKV; kt++) {
        const int j0 = kt * BKV;
        // Load K transposed, V natural
        for (int i = tid; i < BKV * (DK / 4); i += 256) {
            int r  = i >> 4;
            int c4 = (i & 15) * 4;
            float4 kv = *(const float4*)&kbase[(size_t)(j0 + r) * DM + c4];
            Kt[(c4 + 0) * QS + r] = kv.x;
            Kt[(c4 + 1) * QS + r] = kv.y;
            Kt[(c4 + 2) * QS + r] = kv.z;
            Kt[(c4 + 3) * QS + r] = kv.w;
            *(float4*)&Vs[r * DK + c4] =
                *(const float4*)&vbase[(size_t)(j0 + r) * DM + c4];
        }
        __syncthreads();

        // Scores: s[i][p] = sum_d Q[q0+ty*4+i][d] * K[j0+tx*4+p][d]
        float s[4][4];
        #pragma unroll
        for (int i = 0; i < 4; i++)
            #pragma unroll
            for (int p = 0; p < 4; p++) s[i][p] = 0.f;

        #pragma unroll 8
        for (int d = 0; d < DK; d++) {
            float4 a = *(const float4*)&Qt[d * QS + ty * 4];
            float4 k4 = *(const float4*)&Kt[d * QS + tx * 4];
            float ra[4] = {a.x, a.y, a.z, a.w};
            float rk[4] = {k4.x, k4.y, k4.z, k4.w};
            #pragma unroll
            for (int i = 0; i < 4; i++)
                #pragma unroll
                for (int p = 0; p < 4; p++)
                    s[i][p] += ra[i] * rk[p];
        }

        // Online softmax update
        #pragma unroll
        for (int i = 0; i < 4; i++) {
            #pragma unroll
            for (int p = 0; p < 4; p++) s[i][p] *= scale;

            float rmax = fmaxf(fmaxf(s[i][0], s[i][1]), fmaxf(s[i][2], s[i][3]));
            #pragma unroll
            for (int off = 8; off > 0; off >>= 1)
                rmax = fmaxf(rmax, __shfl_xor_sync(0xffffffffu, rmax, off));

            float mnew = fmaxf(m[i], rmax);
            float f = __expf(m[i] - mnew);
            m[i] = mnew;

            float rs = 0.f;
            #pragma unroll
            for (int p = 0; p < 4; p++) {
                s[i][p] = __expf(s[i][p] - mnew);
                rs += s[i][p];
            }
            #pragma unroll
            for (int off = 8; off > 0; off >>= 1)
                rs += __shfl_xor_sync(0xffffffffu, rs, off);

            l[i] = l[i] * f + rs;
            #pragma unroll
            for (int p = 0; p < 4; p++) accO[i][p] *= f;

            // Stage P transposed: Pt[j][r]
            #pragma unroll
            for (int p = 0; p < 4; p++)
                Pt[(tx * 4 + p) * QS + ty * 4 + i] = s[i][p];
        }
        __syncthreads();

        // accO[i][p] += sum_j P[r][j] * V[j][d]
        #pragma unroll 8
        for (int j = 0; j < BKV; j++) {
            float4 pv = *(const float4*)&Pt[j * QS + ty * 4];
            float4 vv = *(const float4*)&Vs[j * DK + tx * 4];
            float rp[4] = {pv.x, pv.y, pv.z, pv.w};
            float rv[4] = {vv.x, vv.y, vv.z, vv.w};
            #pragma unroll
            for (int i = 0; i < 4; i++)
                #pragma unroll
                for (int p = 0; p < 4; p++)
                    accO[i][p] += rp[i] * rv[p];
        }
        __syncthreads();
    }

    // Normalize and write out: [B,S,DM] layout (head h occupies cols h*64..)
    float* obase = gout + (size_t)b * SEQ * DM + head_off;
    #pragma unroll
    for (int i = 0; i < 4; i++) {
        float inv = 1.f / l[i];
        float4 o;
        o.x = accO[i][0] * inv;
        o.y = accO[i][1] * inv;
        o.z = accO[i][2] * inv;
        o.w = accO[i][3] * inv;
        *(float4*)&obase[(size_t)(q0 + ty * 4 + i) * DM + tx * 4] = o;
    }
}

// ---------------- launch -----------------------------------------------------
extern "C" void kernel_launch(void* const* d_in, const int* in_sizes, int n_in,
                              void* d_out, int out_size)
{
    const float* Q  = (const float*)d_in[0];
    const float* K  = (const float*)d_in[1];
    const float* V  = (const float*)d_in[2];
    const float* Wq = (const float*)d_in[3];
    const float* bq = (const float*)d_in[4];
    const float* Wk = (const float*)d_in[5];
    const float* bk = (const float*)d_in[6];
    const float* Wv = (const float*)d_in[7];
    const float* bv = (const float*)d_in[8];
    const float* Wo = (const float*)d_in[9];
    const float* bo = (const float*)d_in[10];
    float* out = (float*)d_out;

    void *pq, *pk, *pv, *pa;
    cudaGetSymbolAddress(&pq, g_q);
    cudaGetSymbolAddress(&pk, g_k);
    cudaGetSymbolAddress(&pv, g_v);
    cudaGetSymbolAddress(&pa, g_attn);

    // Opt-in to >48KB dynamic smem exactly once, on the first (non-captured,
    // correctness) call. Subsequent capture calls perform launches only.
    static bool attr_set = false;
    if (!attr_set) {
        cudaFuncSetAttribute(attn_kernel,
                             cudaFuncAttributeMaxDynamicSharedMemorySize,
                             (int)ATTN_SMEM);
        attr_set = true;
    }

    dim3 pgrid(DM / PN, MROWS / PM);   // (8, 64)
    dim3 pblock(256);

    gemm_bias_kernel<<<pgrid, pblock>>>(Q, Wq, bq, (float*)pq, MROWS, DM, DM);
    gemm_bias_kernel<<<pgrid, pblock>>>(K, Wk, bk, (float*)pk, MROWS, DM, DM);
    gemm_bias_kernel<<<pgrid, pblock>>>(V, Wv, bv, (float*)pv, MROWS, DM, DM);

    dim3 agrid(SEQ / BQ, BATCH * NH);  // (32, 64)
    attn_kernel<<<agrid, 256, ATTN_SMEM>>>((const float*)pq, (const float*)pk,
                                           (const float*)pv, (float*)pa);

    gemm_bias_kernel<<<pgrid, pblock>>>((const float*)pa, Wo, bo, out, MROWS, DM, DM);
}